// round 14
// baseline (speedup 1.0000x reference)
#include <cuda_runtime.h>
#include <stdint.h>

// ============================================================================
// Colorization L2Loss, two kernels.
//   loss = mean_b sum_{c,h,w} (in-tgt)^2 * prior[argmin_q d2(tgt_px, gamut[q])]
//
// Cell mapping (round-to-nearest, FP-magic): m = round(t*31.4) + 32 in [1,63],
//   as bits(fmaf(t, 31.4, 12582944.0)) & 63. Cell center t_c = (m-32)/31.4,
//   half-width r = 0.51/31.4 (inflated for binning FP slop).
// Build: candidate filter = EXACT corner/halfplane test: bin b can be the NN
//   of some p in the cell iff halfplane {d(.,b) <= d(.,b*)} (b* = NN of the
//   center) intersects the cell square, iff it contains one of the 4 corners:
//   exists corner k with d2(k,b) <= d2(k,b*) + eps.  (Necessary condition =>
//   provable NN superset; ascending index order preserved.)
//   Emits u64/cell: 4 x u16 indices dup-padded; slot3 sentinel 0xFFFF =>
//   overflow (P ~ 2%), full list in g_cand/g_cnt.
// Loss (512 blk x 512 thr, 1 px/thread): prefetch pixel scalars, copy 32KB
//   pack + float2 gamut + 0.25-scaled weights to smem, then per px:
//   FFMA/LOP cell -> LDS.64 pack -> 4x LDS.64 gathers -> direct d2 evals ->
//   LDS.32 weight. Exact strict-< argmin, ascending index (= argmin tiebreak).
//   512-thread blocks lift occupancy to ~55 warps/SM (grid was the limiter).
// ============================================================================

#define LGRID 64
#define NCELL (LGRID * LGRID)
#define CAP   32
#define MAXQ  320          // >= Q=313, exactly 10 warp-iterations
#define CINV  (1.0f / 31.4f)
#define CMAGIC 12582944.0f // 2^23 + 2^22 + 32
#define CRAD  (0.51f / 31.4f)

__device__ unsigned long long g_pack[NCELL];    // 32 KB
__device__ unsigned short     g_cand[NCELL * CAP];
__device__ unsigned int       g_cnt[NCELL];

// ---------------------------------------------------------------------------
__global__ void __launch_bounds__(256) build_lut_kernel(
    const float2* __restrict__ gamut, float* __restrict__ out, int Q)
{
    __shared__ float2 sg[MAXQ];
    __shared__ unsigned short scand[8][CAP];

    for (int i = threadIdx.x; i < Q; i += 256) sg[i] = gamut[i];
    __syncthreads();

    if (blockIdx.x == 0 && threadIdx.x == 0) out[0] = 0.0f;

    const int warp = threadIdx.x >> 5;
    const int lane = threadIdx.x & 31;
    const int cell = blockIdx.x * 8 + warp;       // 512*8 = 4096 exactly

    const int ix = cell & (LGRID - 1);
    const int iy = cell >> 6;
    const float cx = (float)(ix - 32) * CINV;     // round-to-nearest bin center
    const float cy = (float)(iy - 32) * CINV;

    // --- exact NN of the center (lowest index on ties) -------------------
    float d2v[MAXQ / 32];
    unsigned long long bkey = ~0ull;
    #pragma unroll
    for (int j = 0; j < MAXQ / 32; j++) {
        const int b = (j << 5) + lane;
        float d2 = 1e30f;
        if (b < Q) {
            const float dx = sg[b].x - cx;
            const float dy = sg[b].y - cy;
            d2 = fmaf(dx, dx, dy * dy);
        }
        d2v[j] = d2;
        const unsigned long long key =
            ((unsigned long long)__float_as_uint(d2) << 32) | (unsigned)b;
        bkey = min(bkey, key);
    }
    #pragma unroll
    for (int off = 16; off; off >>= 1) {
        const unsigned long long o = __shfl_xor_sync(0xFFFFFFFFu, bkey, off);
        bkey = min(bkey, o);
    }
    const int bstar = (int)(bkey & 0xFFFFFFFFull);
    const float2 gb = sg[bstar];

    // d2 of b* at the 4 corners
    const float k0x = cx - CRAD, k1x = cx + CRAD;
    const float k0y = cy - CRAD, k1y = cy + CRAD;
    float bs[4];
    {
        float dx, dy;
        dx = k0x - gb.x; dy = k0y - gb.y; bs[0] = fmaf(dx, dx, dy * dy);
        dx = k1x - gb.x; dy = k0y - gb.y; bs[1] = fmaf(dx, dx, dy * dy);
        dx = k0x - gb.x; dy = k1y - gb.y; bs[2] = fmaf(dx, dx, dy * dy);
        dx = k1x - gb.x; dy = k1y - gb.y; bs[3] = fmaf(dx, dx, dy * dy);
    }
    const float eps = 1e-6f;

    // --- corner filter + ballot compaction -------------------------------
    int base = 0;
    #pragma unroll
    for (int j = 0; j < MAXQ / 32; j++) {
        const int b = (j << 5) + lane;
        bool take = false;
        if (b < Q) {
            const float2 g = sg[b];
            float dx, dy, d;
            dx = k0x - g.x; dy = k0y - g.y; d = fmaf(dx, dx, dy * dy);
            take = (d <= bs[0] + eps);
            dx = k1x - g.x; dy = k0y - g.y; d = fmaf(dx, dx, dy * dy);
            take |= (d <= bs[1] + eps);
            dx = k0x - g.x; dy = k1y - g.y; d = fmaf(dx, dx, dy * dy);
            take |= (d <= bs[2] + eps);
            dx = k1x - g.x; dy = k1y - g.y; d = fmaf(dx, dx, dy * dy);
            take |= (d <= bs[3] + eps);
        }
        const unsigned m = __ballot_sync(0xFFFFFFFFu, take);
        if (take) {
            const int pos = base + __popc(m & ((1u << lane) - 1u));
            if (pos < CAP)
                scand[warp][pos] = (unsigned short)b;
        }
        base += __popc(m);
    }
    __syncwarp();

    if (base > 4) {                               // rare now (~2% of cells)
        const int nw = min(base, CAP);
        for (int j = lane; j < nw; j += 32)
            g_cand[cell * CAP + j] = scand[warp][j];
        if (lane == 0) g_cnt[cell] = (unsigned)base;
    }
    if (lane == 0) {
        const unsigned long long i0 = scand[warp][0];      // base >= 1 (b*)
        const unsigned long long i1 = (base > 1) ? scand[warp][1] : i0;
        const unsigned long long i2 = (base > 2) ? scand[warp][2] : i0;
        unsigned long long i3       = (base > 3) ? scand[warp][3] : i0;
        if (base > 4) i3 = 0xFFFFull;                      // overflow sentinel
        g_pack[cell] = i0 | (i1 << 16) | (i2 << 32) | (i3 << 48);
    }
}

// ---------------------------------------------------------------------------
// Loss: 512 blocks x 512 threads, ONE pixel per thread (262144 px).
// ---------------------------------------------------------------------------
__global__ void __launch_bounds__(512) loss_kernel(
    const float*  __restrict__ input,
    const float*  __restrict__ target,
    const float2* __restrict__ gamut,
    const float*  __restrict__ prior,
    float*        __restrict__ out,
    int Q)
{
    __shared__ unsigned long long spack[NCELL];   // 32 KB
    __shared__ float2 ssg[MAXQ];                  // 2.5 KB raw gamut points
    __shared__ float  ssw[MAXQ];                  // 1.25 KB weights (x0.25)
    __shared__ float  ws[16];

    // Prefetch the pixel scalars FIRST: latency hides under the table copy.
    const int q     = blockIdx.x * 512 + threadIdx.x;   // 0..262143
    const int bb    = q >> 16;
    const int n     = q & 65535;
    const int base0 = bb * 131072 + n;

    const float t0 = target[base0];
    const float t1 = target[base0 + 65536];
    const float i0 = input[base0];
    const float i1 = input[base0 + 65536];

    // copy pack table: 4096 u64 = 2048 uint4; 512 threads -> 4 iters
    {
        const uint4* src = (const uint4*)g_pack;
        uint4* dst = (uint4*)spack;
        #pragma unroll
        for (int j = 0; j < 4; j++)
            dst[threadIdx.x + j * 512] = src[threadIdx.x + j * 512];
    }
    for (int i = threadIdx.x; i < Q; i += 512) {
        ssg[i] = gamut[i];
        ssw[i] = prior[i] * 0.25f;    // fold batch mean into the weight
    }
    __syncthreads();

    // Magic-number cell binning: m = round(31.4*t) + 32 in [1,63] = bits & 63.
    const int ixp = (int)(__float_as_uint(fmaf(t0, 31.4f, CMAGIC)) & 63u);
    const int iyp = (int)(__float_as_uint(fmaf(t1, 31.4f, CMAGIC)) & 63u);
    const int cc  = (iyp << 6) | ixp;

    const unsigned long long p = spack[cc];
    const unsigned a0 = (unsigned)(p & 0xFFFFull);
    const unsigned a1 = (unsigned)((p >> 16) & 0xFFFFull);
    const unsigned a2 = (unsigned)((p >> 32) & 0xFFFFull);
    const unsigned a3 = (unsigned)(p >> 48);

    float w;
    if (a3 != 0xFFFFu) {
        float2 g = ssg[a0];
        float dx = t0 - g.x, dy = t1 - g.y;
        float best = fmaf(dx, dx, dy * dy);
        unsigned bi = a0;

        g = ssg[a1]; dx = t0 - g.x; dy = t1 - g.y;
        float d = fmaf(dx, dx, dy * dy);
        if (d < best) { best = d; bi = a1; }

        g = ssg[a2]; dx = t0 - g.x; dy = t1 - g.y;
        d = fmaf(dx, dx, dy * dy);
        if (d < best) { best = d; bi = a2; }

        g = ssg[a3]; dx = t0 - g.x; dy = t1 - g.y;
        d = fmaf(dx, dx, dy * dy);
        if (d < best) { best = d; bi = a3; }

        w = ssw[bi];
    } else {
        // rare overflow cell (~2%): exact scan of the global list
        float best = 1e30f;
        unsigned bi = 0;
        const unsigned cnt = g_cnt[cc];
        if (cnt <= CAP) {
            const unsigned short* cl = &g_cand[cc * CAP];
            for (unsigned j = 0; j < cnt; j++) {
                const unsigned b = (unsigned)cl[j];
                const float2 g = ssg[b];
                const float dx = t0 - g.x, dy = t1 - g.y;
                const float d = fmaf(dx, dx, dy * dy);
                if (d < best) { best = d; bi = b; }
            }
        } else {
            for (int b = 0; b < Q; b++) {
                const float2 g = ssg[b];
                const float dx = t0 - g.x, dy = t1 - g.y;
                const float d = fmaf(dx, dx, dy * dy);
                if (d < best) { best = d; bi = (unsigned)b; }
            }
        }
        w = ssw[bi];
    }

    const float d0 = i0 - t0;
    const float d1 = i1 - t1;
    float acc = w * fmaf(d0, d0, d1 * d1);

    #pragma unroll
    for (int off = 16; off; off >>= 1)
        acc += __shfl_xor_sync(0xFFFFFFFFu, acc, off);

    if ((threadIdx.x & 31) == 0) ws[threadIdx.x >> 5] = acc;
    __syncthreads();
    if (threadIdx.x < 16) {
        float v = ws[threadIdx.x];
        #pragma unroll
        for (int off = 8; off; off >>= 1)
            v += __shfl_xor_sync(0xFFFFu, v, off);
        if (threadIdx.x == 0) atomicAdd(out, v);
    }
}

// ---------------------------------------------------------------------------
extern "C" void kernel_launch(void* const* d_in, const int* in_sizes, int n_in,
                              void* d_out, int out_size)
{
    const float*  input  = (const float*)d_in[0];
    const float*  target = (const float*)d_in[1];
    const float2* gamut  = (const float2*)d_in[2];   // [Q,2]
    const float*  prior  = (const float*)d_in[3];    // [Q]
    float* out = (float*)d_out;
    const int Q = in_sizes[3];                        // 313

    build_lut_kernel<<<NCELL / 8, 256>>>(gamut, out, Q);
    loss_kernel<<<512, 512>>>(input, target, gamut, prior, out, Q);
}

// round 15
// speedup vs baseline: 1.1600x; 1.1600x over previous
#include <cuda_runtime.h>
#include <stdint.h>

// ============================================================================
// Colorization L2Loss, two kernels.
//   loss = mean_b sum_{c,h,w} (in-tgt)^2 * prior[argmin_q d2(tgt_px, gamut[q])]
//
// Cell mapping (round-to-nearest, FP-magic): m = round(t*31.4) + 32 in [1,63],
//   as bits(fmaf(t, 31.4, 12582944.0)) & 63. Cell center t_c = (m-32)/31.4,
//   half-width r = 0.51/31.4 (inflated for binning FP slop).
// Build candidate filter (analytic 4-corner halfplane test): for reference bin
//   b̂, min over the 4 cell corners k of [d2(k,b) - d2(k,b̂)] equals
//   d2(c,b) - d2(c,b̂) - 2r(|Δx|+|Δy|), Δ = b - b̂. So b is a candidate iff
//   d2(c,b) <= d2(c,b̂) + 2r(|Δx|+|Δy|) + eps. Valid NN-superset for ANY b̂
//   (b NN of p => d(p,b) <= d(p,b̂)); we pick b̂ ~ argmin via a packed 32-bit
//   key reduce, then use its EXACT center distance. Ascending index order.
//   Emits u64/cell: 4 x u16 dup-padded; slot3 sentinel 0xFFFF => overflow
//   (~2% of cells), full list in g_cand/g_cnt.
// Loss (512 blk x 512 thr, 1 px/thread — measured 8.0us, occ 80%): prefetch
//   pixel scalars, copy 32KB pack + float2 gamut + 0.25-scaled weights to
//   smem, then: FFMA/LOP cell -> LDS.64 pack -> 4x LDS.64 gathers -> direct
//   d2 evals -> LDS.32 weight. Exact strict-< argmin (= argmin tie-break).
// ============================================================================

#define LGRID 64
#define NCELL (LGRID * LGRID)
#define CAP   32
#define MAXQ  320          // >= Q=313, exactly 10 warp-iterations
#define CINV  (1.0f / 31.4f)
#define CMAGIC 12582944.0f // 2^23 + 2^22 + 32
#define CRAD  (0.51f / 31.4f)
#define TWOR  (2.0f * CRAD)

__device__ unsigned long long g_pack[NCELL];    // 32 KB
__device__ unsigned short     g_cand[NCELL * CAP];
__device__ unsigned int       g_cnt[NCELL];

// ---------------------------------------------------------------------------
__global__ void __launch_bounds__(256) build_lut_kernel(
    const float2* __restrict__ gamut, float* __restrict__ out, int Q)
{
    __shared__ float2 sg[MAXQ];
    __shared__ unsigned short scand[8][CAP];

    for (int i = threadIdx.x; i < Q; i += 256) sg[i] = gamut[i];
    __syncthreads();

    if (blockIdx.x == 0 && threadIdx.x == 0) out[0] = 0.0f;

    const int warp = threadIdx.x >> 5;
    const int lane = threadIdx.x & 31;
    const int cell = blockIdx.x * 8 + warp;       // 512*8 = 4096 exactly

    const int ix = cell & (LGRID - 1);
    const int iy = cell >> 6;
    const float cx = (float)(ix - 32) * CINV;     // round-to-nearest bin center
    const float cy = (float)(iy - 32) * CINV;

    // --- pass 1: center distances + approx-argmin via packed 32-bit key ----
    float d2v[MAXQ / 32];
    unsigned bkey = 0xFFFFFFFFu;
    #pragma unroll
    for (int j = 0; j < MAXQ / 32; j++) {
        const int b = (j << 5) + lane;
        float d2 = 1e30f;
        if (b < Q) {
            const float dx = sg[b].x - cx;
            const float dy = sg[b].y - cy;
            d2 = fmaf(dx, dx, dy * dy);
        }
        d2v[j] = d2;
        // positive floats order as uints; low 9 bits carry the index.
        // approx argmin is fine: the filter is valid for ANY reference bin.
        bkey = min(bkey, (__float_as_uint(d2) & 0xFFFFFE00u) | (unsigned)b);
    }
    #pragma unroll
    for (int off = 16; off; off >>= 1)
        bkey = min(bkey, __shfl_xor_sync(0xFFFFFFFFu, bkey, off));

    const int bhat = (int)(bkey & 0x1FFu);
    const float2 gb = sg[bhat];
    float thr;
    {
        const float dx = gb.x - cx;
        const float dy = gb.y - cy;
        thr = fmaf(dx, dx, dy * dy) + 1e-5f;      // exact d2(c,b̂) + eps
    }

    // --- pass 2: analytic corner filter + ballot compaction ----------------
    int base = 0;
    #pragma unroll
    for (int j = 0; j < MAXQ / 32; j++) {
        const int b = (j << 5) + lane;
        const float2 g = sg[b < Q ? b : 0];
        const float s = fabsf(g.x - gb.x) + fabsf(g.y - gb.y);
        const bool take = (d2v[j] <= fmaf(TWOR, s, thr));   // d2v=1e30 if b>=Q
        const unsigned m = __ballot_sync(0xFFFFFFFFu, take);
        if (take) {
            const int pos = base + __popc(m & ((1u << lane) - 1u));
            if (pos < CAP)
                scand[warp][pos] = (unsigned short)b;
        }
        base += __popc(m);
    }
    __syncwarp();

    if (base > 4) {                               // rare (~2% of cells)
        const int nw = min(base, CAP);
        for (int j = lane; j < nw; j += 32)
            g_cand[cell * CAP + j] = scand[warp][j];
        if (lane == 0) g_cnt[cell] = (unsigned)base;
    }
    if (lane == 0) {
        const unsigned long long i0 = scand[warp][0];      // base >= 1 (b̂)
        const unsigned long long i1 = (base > 1) ? scand[warp][1] : i0;
        const unsigned long long i2 = (base > 2) ? scand[warp][2] : i0;
        unsigned long long i3       = (base > 3) ? scand[warp][3] : i0;
        if (base > 4) i3 = 0xFFFFull;                      // overflow sentinel
        g_pack[cell] = i0 | (i1 << 16) | (i2 << 32) | (i3 << 48);
    }
}

// ---------------------------------------------------------------------------
// Loss: 512 blocks x 512 threads, ONE pixel per thread (262144 px).
// ---------------------------------------------------------------------------
__global__ void __launch_bounds__(512) loss_kernel(
    const float*  __restrict__ input,
    const float*  __restrict__ target,
    const float2* __restrict__ gamut,
    const float*  __restrict__ prior,
    float*        __restrict__ out,
    int Q)
{
    __shared__ unsigned long long spack[NCELL];   // 32 KB
    __shared__ float2 ssg[MAXQ];                  // 2.5 KB raw gamut points
    __shared__ float  ssw[MAXQ];                  // 1.25 KB weights (x0.25)
    __shared__ float  ws[16];

    // Prefetch the pixel scalars FIRST: latency hides under the table copy.
    const int q     = blockIdx.x * 512 + threadIdx.x;   // 0..262143
    const int bb    = q >> 16;
    const int n     = q & 65535;
    const int base0 = bb * 131072 + n;

    const float t0 = target[base0];
    const float t1 = target[base0 + 65536];
    const float i0 = input[base0];
    const float i1 = input[base0 + 65536];

    // copy pack table: 4096 u64 = 2048 uint4; 512 threads -> 4 iters
    {
        const uint4* src = (const uint4*)g_pack;
        uint4* dst = (uint4*)spack;
        #pragma unroll
        for (int j = 0; j < 4; j++)
            dst[threadIdx.x + j * 512] = src[threadIdx.x + j * 512];
    }
    for (int i = threadIdx.x; i < Q; i += 512) {
        ssg[i] = gamut[i];
        ssw[i] = prior[i] * 0.25f;    // fold batch mean into the weight
    }
    __syncthreads();

    // Magic-number cell binning: m = round(31.4*t) + 32 in [1,63] = bits & 63.
    const int ixp = (int)(__float_as_uint(fmaf(t0, 31.4f, CMAGIC)) & 63u);
    const int iyp = (int)(__float_as_uint(fmaf(t1, 31.4f, CMAGIC)) & 63u);
    const int cc  = (iyp << 6) | ixp;

    const unsigned long long p = spack[cc];
    const unsigned a0 = (unsigned)(p & 0xFFFFull);
    const unsigned a1 = (unsigned)((p >> 16) & 0xFFFFull);
    const unsigned a2 = (unsigned)((p >> 32) & 0xFFFFull);
    const unsigned a3 = (unsigned)(p >> 48);

    float w;
    if (a3 != 0xFFFFu) {
        float2 g = ssg[a0];
        float dx = t0 - g.x, dy = t1 - g.y;
        float best = fmaf(dx, dx, dy * dy);
        unsigned bi = a0;

        g = ssg[a1]; dx = t0 - g.x; dy = t1 - g.y;
        float d = fmaf(dx, dx, dy * dy);
        if (d < best) { best = d; bi = a1; }

        g = ssg[a2]; dx = t0 - g.x; dy = t1 - g.y;
        d = fmaf(dx, dx, dy * dy);
        if (d < best) { best = d; bi = a2; }

        g = ssg[a3]; dx = t0 - g.x; dy = t1 - g.y;
        d = fmaf(dx, dx, dy * dy);
        if (d < best) { best = d; bi = a3; }

        w = ssw[bi];
    } else {
        // rare overflow cell (~2%): exact scan of the global list
        float best = 1e30f;
        unsigned bi = 0;
        const unsigned cnt = g_cnt[cc];
        if (cnt <= CAP) {
            const unsigned short* cl = &g_cand[cc * CAP];
            for (unsigned j = 0; j < cnt; j++) {
                const unsigned b = (unsigned)cl[j];
                const float2 g = ssg[b];
                const float dx = t0 - g.x, dy = t1 - g.y;
                const float d = fmaf(dx, dx, dy * dy);
                if (d < best) { best = d; bi = b; }
            }
        } else {
            for (int b = 0; b < Q; b++) {
                const float2 g = ssg[b];
                const float dx = t0 - g.x, dy = t1 - g.y;
                const float d = fmaf(dx, dx, dy * dy);
                if (d < best) { best = d; bi = (unsigned)b; }
            }
        }
        w = ssw[bi];
    }

    const float d0 = i0 - t0;
    const float d1 = i1 - t1;
    float acc = w * fmaf(d0, d0, d1 * d1);

    #pragma unroll
    for (int off = 16; off; off >>= 1)
        acc += __shfl_xor_sync(0xFFFFFFFFu, acc, off);

    if ((threadIdx.x & 31) == 0) ws[threadIdx.x >> 5] = acc;
    __syncthreads();
    if (threadIdx.x < 16) {
        float v = ws[threadIdx.x];
        #pragma unroll
        for (int off = 8; off; off >>= 1)
            v += __shfl_xor_sync(0xFFFFu, v, off);
        if (threadIdx.x == 0) atomicAdd(out, v);
    }
}

// ---------------------------------------------------------------------------
extern "C" void kernel_launch(void* const* d_in, const int* in_sizes, int n_in,
                              void* d_out, int out_size)
{
    const float*  input  = (const float*)d_in[0];
    const float*  target = (const float*)d_in[1];
    const float2* gamut  = (const float2*)d_in[2];   // [Q,2]
    const float*  prior  = (const float*)d_in[3];    // [Q]
    float* out = (float*)d_out;
    const int Q = in_sizes[3];                        // 313

    build_lut_kernel<<<NCELL / 8, 256>>>(gamut, out, Q);
    loss_kernel<<<512, 512>>>(input, target, gamut, prior, out, Q);
}

// round 16
// speedup vs baseline: 1.1629x; 1.0025x over previous
#include <cuda_runtime.h>
#include <stdint.h>

// ============================================================================
// Colorization L2Loss, two kernels.
//   loss = mean_b sum_{c,h,w} (in-tgt)^2 * prior[argmin_q d2(tgt_px, gamut[q])]
//
// Cell mapping (round-to-nearest, FP-magic): m = round(t*31.4) + 32 in [1,63],
//   as bits(fmaf(t, 31.4, 12582944.0)) & 63. Cell center t_c = (m-32)/31.4,
//   half-width r = 0.51/31.4 (inflated for binning FP slop).
// Build candidate filter (analytic 4-corner halfplane test): for reference bin
//   b̂, min over the 4 cell corners k of [d2(k,b) - d2(k,b̂)] equals
//   d2(c,b) - d2(c,b̂) - 2r(|Δx|+|Δy|), Δ = b - b̂. So b is a candidate iff
//   d2(c,b) <= d2(c,b̂) + 2r(|Δx|+|Δy|) + eps. Valid NN-superset for ANY b̂;
//   b̂ ~ argmin via packed 32-bit key reduce, exact d2(c,b̂) recomputed.
//   Pass 2 is REGISTER-ONLY: gamut coords cached in regs during pass 1
//   (no smem re-gather). Emits u64/cell: 4 x u16 dup-padded ascending;
//   slot3 sentinel 0xFFFF => overflow (~2%), full list in g_cand/g_cnt.
// Loss (512 blk x 512 thr, 1 px/thread — measured 7.74us, occ 81%): prefetch
//   pixel scalars, copy 32KB pack + float2 gamut + 0.25-scaled weights to
//   smem, then: FFMA/LOP cell -> LDS.64 pack -> 4x LDS.64 gathers -> direct
//   d2 evals -> LDS.32 weight. Exact strict-< argmin (= argmin tie-break).
// ============================================================================

#define LGRID 64
#define NCELL (LGRID * LGRID)
#define CAP   32
#define MAXQ  320          // >= Q=313, exactly 10 warp-iterations
#define NIT   (MAXQ / 32)
#define CINV  (1.0f / 31.4f)
#define CMAGIC 12582944.0f // 2^23 + 2^22 + 32
#define CRAD  (0.51f / 31.4f)
#define TWOR  (2.0f * CRAD)

__device__ unsigned long long g_pack[NCELL];    // 32 KB
__device__ unsigned short     g_cand[NCELL * CAP];
__device__ unsigned int       g_cnt[NCELL];

// ---------------------------------------------------------------------------
__global__ void __launch_bounds__(256) build_lut_kernel(
    const float2* __restrict__ gamut, float* __restrict__ out, int Q)
{
    __shared__ float2 sg[MAXQ];
    __shared__ unsigned short scand[8][CAP];

    if (blockIdx.x == 0 && threadIdx.x == 0) out[0] = 0.0f;

    for (int i = threadIdx.x; i < Q; i += 256) sg[i] = gamut[i];
    __syncthreads();

    const int warp = threadIdx.x >> 5;
    const int lane = threadIdx.x & 31;
    const int cell = blockIdx.x * 8 + warp;       // 512*8 = 4096 exactly

    const int ix = cell & (LGRID - 1);
    const int iy = cell >> 6;
    const float cx = (float)(ix - 32) * CINV;     // round-to-nearest bin center
    const float cy = (float)(iy - 32) * CINV;

    // --- pass 1: gather coords into REGISTERS, center d2, packed-key argmin
    float gx[NIT], gy[NIT], d2v[NIT];
    unsigned bkey = 0xFFFFFFFFu;
    #pragma unroll
    for (int j = 0; j < NIT; j++) {
        const int b = (j << 5) + lane;
        const float2 g = sg[b < Q ? b : 0];
        gx[j] = g.x;
        gy[j] = g.y;
        float d2 = 1e30f;
        if (b < Q) {
            const float dx = g.x - cx;
            const float dy = g.y - cy;
            d2 = fmaf(dx, dx, dy * dy);
        }
        d2v[j] = d2;
        // positive floats order as uints; low 9 bits carry the index.
        // approx argmin is fine: the filter is valid for ANY reference bin.
        bkey = min(bkey, (__float_as_uint(d2) & 0xFFFFFE00u) | (unsigned)b);
    }
    #pragma unroll
    for (int off = 16; off; off >>= 1)
        bkey = min(bkey, __shfl_xor_sync(0xFFFFFFFFu, bkey, off));

    const int bhat = (int)(bkey & 0x1FFu);
    const float2 gb = sg[bhat];
    float thr;
    {
        const float dx = gb.x - cx;
        const float dy = gb.y - cy;
        thr = fmaf(dx, dx, dy * dy) + 1e-5f;      // exact d2(c,b̂) + eps
    }

    // --- pass 2: register-only analytic corner filter + ballot compaction --
    int base = 0;
    #pragma unroll
    for (int j = 0; j < NIT; j++) {
        const float s = fabsf(gx[j] - gb.x) + fabsf(gy[j] - gb.y);
        const bool take = (d2v[j] <= fmaf(TWOR, s, thr));   // d2v=1e30 if b>=Q
        const unsigned m = __ballot_sync(0xFFFFFFFFu, take);
        if (take) {
            const int pos = base + __popc(m & ((1u << lane) - 1u));
            if (pos < CAP)
                scand[warp][pos] = (unsigned short)((j << 5) + lane);
        }
        base += __popc(m);
    }
    __syncwarp();

    if (base > 4) {                               // rare (~2% of cells)
        const int nw = min(base, CAP);
        for (int j = lane; j < nw; j += 32)
            g_cand[cell * CAP + j] = scand[warp][j];
        if (lane == 0) g_cnt[cell] = (unsigned)base;
    }
    if (lane == 0) {
        const unsigned long long i0 = scand[warp][0];      // base >= 1 (b̂)
        const unsigned long long i1 = (base > 1) ? scand[warp][1] : i0;
        const unsigned long long i2 = (base > 2) ? scand[warp][2] : i0;
        unsigned long long i3       = (base > 3) ? scand[warp][3] : i0;
        if (base > 4) i3 = 0xFFFFull;                      // overflow sentinel
        g_pack[cell] = i0 | (i1 << 16) | (i2 << 32) | (i3 << 48);
    }
}

// ---------------------------------------------------------------------------
// Loss: 512 blocks x 512 threads, ONE pixel per thread (262144 px).
// (Identical to the R15 kernel measured at 7.74us / occ 81%.)
// ---------------------------------------------------------------------------
__global__ void __launch_bounds__(512) loss_kernel(
    const float*  __restrict__ input,
    const float*  __restrict__ target,
    const float2* __restrict__ gamut,
    const float*  __restrict__ prior,
    float*        __restrict__ out,
    int Q)
{
    __shared__ unsigned long long spack[NCELL];   // 32 KB
    __shared__ float2 ssg[MAXQ];                  // 2.5 KB raw gamut points
    __shared__ float  ssw[MAXQ];                  // 1.25 KB weights (x0.25)
    __shared__ float  ws[16];

    // Prefetch the pixel scalars FIRST: latency hides under the table copy.
    const int q     = blockIdx.x * 512 + threadIdx.x;   // 0..262143
    const int bb    = q >> 16;
    const int n     = q & 65535;
    const int base0 = bb * 131072 + n;

    const float t0 = target[base0];
    const float t1 = target[base0 + 65536];
    const float i0 = input[base0];
    const float i1 = input[base0 + 65536];

    // copy pack table: 4096 u64 = 2048 uint4; 512 threads -> 4 iters
    {
        const uint4* src = (const uint4*)g_pack;
        uint4* dst = (uint4*)spack;
        #pragma unroll
        for (int j = 0; j < 4; j++)
            dst[threadIdx.x + j * 512] = src[threadIdx.x + j * 512];
    }
    for (int i = threadIdx.x; i < Q; i += 512) {
        ssg[i] = gamut[i];
        ssw[i] = prior[i] * 0.25f;    // fold batch mean into the weight
    }
    __syncthreads();

    // Magic-number cell binning: m = round(31.4*t) + 32 in [1,63] = bits & 63.
    const int ixp = (int)(__float_as_uint(fmaf(t0, 31.4f, CMAGIC)) & 63u);
    const int iyp = (int)(__float_as_uint(fmaf(t1, 31.4f, CMAGIC)) & 63u);
    const int cc  = (iyp << 6) | ixp;

    const unsigned long long p = spack[cc];
    const unsigned a0 = (unsigned)(p & 0xFFFFull);
    const unsigned a1 = (unsigned)((p >> 16) & 0xFFFFull);
    const unsigned a2 = (unsigned)((p >> 32) & 0xFFFFull);
    const unsigned a3 = (unsigned)(p >> 48);

    float w;
    if (a3 != 0xFFFFu) {
        float2 g = ssg[a0];
        float dx = t0 - g.x, dy = t1 - g.y;
        float best = fmaf(dx, dx, dy * dy);
        unsigned bi = a0;

        g = ssg[a1]; dx = t0 - g.x; dy = t1 - g.y;
        float d = fmaf(dx, dx, dy * dy);
        if (d < best) { best = d; bi = a1; }

        g = ssg[a2]; dx = t0 - g.x; dy = t1 - g.y;
        d = fmaf(dx, dx, dy * dy);
        if (d < best) { best = d; bi = a2; }

        g = ssg[a3]; dx = t0 - g.x; dy = t1 - g.y;
        d = fmaf(dx, dx, dy * dy);
        if (d < best) { best = d; bi = a3; }

        w = ssw[bi];
    } else {
        // rare overflow cell (~2%): exact scan of the global list
        float best = 1e30f;
        unsigned bi = 0;
        const unsigned cnt = g_cnt[cc];
        if (cnt <= CAP) {
            const unsigned short* cl = &g_cand[cc * CAP];
            for (unsigned j = 0; j < cnt; j++) {
                const unsigned b = (unsigned)cl[j];
                const float2 g = ssg[b];
                const float dx = t0 - g.x, dy = t1 - g.y;
                const float d = fmaf(dx, dx, dy * dy);
                if (d < best) { best = d; bi = b; }
            }
        } else {
            for (int b = 0; b < Q; b++) {
                const float2 g = ssg[b];
                const float dx = t0 - g.x, dy = t1 - g.y;
                const float d = fmaf(dx, dx, dy * dy);
                if (d < best) { best = d; bi = (unsigned)b; }
            }
        }
        w = ssw[bi];
    }

    const float d0 = i0 - t0;
    const float d1 = i1 - t1;
    float acc = w * fmaf(d0, d0, d1 * d1);

    #pragma unroll
    for (int off = 16; off; off >>= 1)
        acc += __shfl_xor_sync(0xFFFFFFFFu, acc, off);

    if ((threadIdx.x & 31) == 0) ws[threadIdx.x >> 5] = acc;
    __syncthreads();
    if (threadIdx.x < 16) {
        float v = ws[threadIdx.x];
        #pragma unroll
        for (int off = 8; off; off >>= 1)
            v += __shfl_xor_sync(0xFFFFu, v, off);
        if (threadIdx.x == 0) atomicAdd(out, v);
    }
}

// ---------------------------------------------------------------------------
extern "C" void kernel_launch(void* const* d_in, const int* in_sizes, int n_in,
                              void* d_out, int out_size)
{
    const float*  input  = (const float*)d_in[0];
    const float*  target = (const float*)d_in[1];
    const float2* gamut  = (const float2*)d_in[2];   // [Q,2]
    const float*  prior  = (const float*)d_in[3];    // [Q]
    float* out = (float*)d_out;
    const int Q = in_sizes[3];                        // 313

    build_lut_kernel<<<NCELL / 8, 256>>>(gamut, out, Q);
    loss_kernel<<<512, 512>>>(input, target, gamut, prior, out, Q);
}